// round 10
// baseline (speedup 1.0000x reference)
#include <cuda_runtime.h>
#include <cuda_bf16.h>

#define NATOMS 6144
#define F 128
#define G 48
#define MT 32                  // GEMM M tile
#define KC 16                  // GEMM K chunk (B staging)
#define MTILES (NATOMS / MT)   // 192
#define MAXC 256
#define KE_CONST 14.3996f

typedef unsigned long long u64;

// ---------------- scratch ----------------
__device__ float    g_q[NATOMS];
__device__ float    g_sc6[NATOMS];
__device__ float    g_r3[NATOMS];
__device__ int      g_start[G];
__device__ int      g_cnt[G];
__device__ double   g_esum;
__device__ unsigned g_done;

__device__ __forceinline__ float softplusf(float x) {
    return fmaxf(x, 0.0f) + log1pf(expf(-fabsf(x)));
}
__device__ __forceinline__ float siluf(float x) {
    return x / (1.0f + expf(-x));
}

// packed fp32x2 FMA (sm_100+)
#define FMA2(acc, w, x) asm("fma.rn.f32x2 %0, %1, %2, %0;" : "+l"(acc) : "l"(w), "l"(x))

__device__ __forceinline__ u64 dup2(float x) {
    u64 r; asm("mov.b64 %0, {%1,%1};" : "=l"(r) : "f"(x)); return r;
}
__device__ __forceinline__ void unpack2(u64 p, float &lo, float &hi) {
    asm("mov.b64 {%0,%1}, %2;" : "=f"(lo), "=f"(hi) : "l"(p));
}
__device__ __forceinline__ unsigned smem_u32(const void* p) {
    return (unsigned)__cvta_generic_to_shared(p);
}
__device__ __forceinline__ void cp16(unsigned dst, const void* src) {
    asm volatile("cp.async.ca.shared.global [%0], [%1], 16;\n" :: "r"(dst), "l"(src));
}
#define CP_COMMIT() asm volatile("cp.async.commit_group;\n" ::: "memory")
#define CP_WAIT0()  asm volatile("cp.async.wait_group 0;\n" ::: "memory")

// ================= K1: fused MLP GEMM =================
// grid = 2*MTILES + 1 = 385 blocks of 128 threads.
// bid < 2*MTILES: GEMM block (head = bid/MTILES, m-tile = bid%MTILES).
// Last block: segment bounds + accumulator reset.
// Thread layout: ng = tid&15 (8 n-cols -> N=128), mg = tid>>4 (0..7, 4 atoms -> M=32).
// Per-thread register tile: 2 m-pairs x 8 n (u64 accumulators, f32x2 math).
__global__ __launch_bounds__(128) void mlp_gemm_kernel(
    const float* __restrict__ h0,
    const float* __restrict__ qW1, const float* __restrict__ qb1,
    const float* __restrict__ qW2,
    const float* __restrict__ vW1, const float* __restrict__ vb1,
    const float* __restrict__ vW2, const float* __restrict__ vb2,
    const int*   __restrict__ batch)
{
    const int bid = blockIdx.x;
    const int tid = threadIdx.x;

    if (bid == 2 * MTILES) {
        if (tid == 0) { g_esum = 0.0; g_done = 0u; }
        __shared__ int ss[G + 1];
        if (tid <= G) {
            int lo = 0, hi = NATOMS;
            while (lo < hi) {
                int m = (lo + hi) >> 1;
                if (batch[m] < tid) lo = m + 1; else hi = m;
            }
            ss[tid] = lo;
        }
        __syncthreads();
        if (tid < G) { g_start[tid] = ss[tid]; g_cnt[tid] = ss[tid + 1] - ss[tid]; }
        return;
    }

    const int head  = bid / MTILES;          // 0 = charge, 1 = vdw
    const int mbase = (bid % MTILES) * MT;
    const int ng = tid & 15;
    const int mg = tid >> 4;                 // 0..7

    const float* __restrict__ W1 = head ? vW1 : qW1;
    const float* __restrict__ B1 = head ? vb1 : qb1;

    // A: [k][m], 32 atoms per k-row, padded to 34 (8B-aligned pairs)
    __shared__ float As[F][34];
    __shared__ float Bs[2][KC][F];

    // ---- prologue: B chunk 0 via cp.async ----
    {
        unsigned dst = smem_u32(&Bs[0][0][0]);
        const char* src = (const char*)W1;
#pragma unroll
        for (int i = 0; i < 4; i++)
            cp16(dst + (i * 128 + tid) * 16, src + (i * 128 + tid) * 16);
        CP_COMMIT();
    }

    // ---- fill A tile (transpose to [k][m]) ----
    {
        const int atom = tid >> 2;           // 0..31
        const int kq   = (tid & 3) * 32;     // 0,32,64,96
        const float4* src = (const float4*)&h0[(mbase + atom) * F + kq];
#pragma unroll
        for (int kk = 0; kk < 8; kk++) {
            float4 v = src[kk];
            int k = kq + kk * 4;
            As[k + 0][atom] = v.x;
            As[k + 1][atom] = v.y;
            As[k + 2][atom] = v.z;
            As[k + 3][atom] = v.w;
        }
    }

    u64 acc[2][8];
#pragma unroll
    for (int p = 0; p < 2; p++)
#pragma unroll
        for (int j = 0; j < 8; j++) acc[p][j] = 0ull;

    for (int c = 0; c < F / KC; c++) {
        const int buf = c & 1;
        CP_WAIT0();
        __syncthreads();
        if (c < F / KC - 1) {
            unsigned dst = smem_u32(&Bs[buf ^ 1][0][0]);
            const char* src = (const char*)(W1 + (c + 1) * KC * F);
#pragma unroll
            for (int i = 0; i < 4; i++)
                cp16(dst + (i * 128 + tid) * 16, src + (i * 128 + tid) * 16);
            CP_COMMIT();
        }

#pragma unroll
        for (int r = 0; r < KC; r++) {
            const int k = c * KC + r;
            const u64* ap = (const u64*)&As[k][mg * 4];
            u64 a0 = ap[0], a1 = ap[1];
            float4 b03 = *(const float4*)&Bs[buf][r][ng * 8 + 0];
            float4 b47 = *(const float4*)&Bs[buf][r][ng * 8 + 4];
            u64 bb0 = dup2(b03.x), bb1 = dup2(b03.y);
            u64 bb2 = dup2(b03.z), bb3 = dup2(b03.w);
            u64 bb4 = dup2(b47.x), bb5 = dup2(b47.y);
            u64 bb6 = dup2(b47.z), bb7 = dup2(b47.w);
            FMA2(acc[0][0], a0, bb0); FMA2(acc[0][1], a0, bb1);
            FMA2(acc[0][2], a0, bb2); FMA2(acc[0][3], a0, bb3);
            FMA2(acc[0][4], a0, bb4); FMA2(acc[0][5], a0, bb5);
            FMA2(acc[0][6], a0, bb6); FMA2(acc[0][7], a0, bb7);
            FMA2(acc[1][0], a1, bb0); FMA2(acc[1][1], a1, bb1);
            FMA2(acc[1][2], a1, bb2); FMA2(acc[1][3], a1, bb3);
            FMA2(acc[1][4], a1, bb4); FMA2(acc[1][5], a1, bb5);
            FMA2(acc[1][6], a1, bb6); FMA2(acc[1][7], a1, bb7);
        }
        __syncthreads();
    }

    // ---- fused second layer: silu + dot(w2), reduce over ng lanes ----
    const int n0 = ng * 8;
    float b1v[8], w2a[8], w2b[8];
#pragma unroll
    for (int j = 0; j < 8; j++) {
        b1v[j] = B1[n0 + j];
        if (head) { w2a[j] = vW2[2 * (n0 + j)]; w2b[j] = vW2[2 * (n0 + j) + 1]; }
        else      { w2a[j] = qW2[n0 + j];       w2b[j] = 0.0f; }
    }

#pragma unroll
    for (int p = 0; p < 2; p++) {
        float s0a = 0.f, s1a = 0.f, s0b = 0.f, s1b = 0.f;
#pragma unroll
        for (int j = 0; j < 8; j++) {
            float ya, yb; unpack2(acc[p][j], ya, yb);
            float ha = siluf(ya + b1v[j]);
            float hb = siluf(yb + b1v[j]);
            s0a += ha * w2a[j]; s1a += ha * w2b[j];
            s0b += hb * w2a[j]; s1b += hb * w2b[j];
        }
        // reduce over the 16-lane ng group (xor masks stay inside the group)
#pragma unroll
        for (int m = 8; m >= 1; m >>= 1) {
            s0a += __shfl_xor_sync(0xFFFFFFFFu, s0a, m);
            s1a += __shfl_xor_sync(0xFFFFFFFFu, s1a, m);
            s0b += __shfl_xor_sync(0xFFFFFFFFu, s0b, m);
            s1b += __shfl_xor_sync(0xFFFFFFFFu, s1b, m);
        }
        if (ng == 0) {
            int a0i = mbase + mg * 4 + 2 * p;
            if (head == 0) {
                g_q[a0i]     = s0a;
                g_q[a0i + 1] = s0b;
            } else {
                float c6a = softplusf(s0a + vb2[0]);
                float rva = softplusf(s1a + vb2[1]);
                g_sc6[a0i] = sqrtf(c6a);
                g_r3[a0i]  = rva * rva * rva;
                float c6b = softplusf(s0b + vb2[0]);
                float rvb = softplusf(s1b + vb2[1]);
                g_sc6[a0i + 1] = sqrtf(c6b);
                g_r3[a0i + 1]  = rvb * rvb * rvb;
            }
        }
    }
}

// ================= K2: pairwise, one block per graph =================
__global__ __launch_bounds__(256) void pair_kernel(
    const float* __restrict__ pos,
    const float* __restrict__ sigma,
    float* __restrict__ out)
{
    __shared__ float sx[MAXC], sy[MAXC], sz[MAXC];
    __shared__ float sq[MAXC], sc[MAXC], sr[MAXC];
    __shared__ float wred[8];
    __shared__ float s_qm;

    const int g   = blockIdx.x;
    const int tid = threadIdx.x;
    const int lane = tid & 31;
    const int wrp  = tid >> 5;

    const int s = g_start[g];
    const int c = g_cnt[g];

    float qacc = 0.f;
    for (int t = tid; t < c; t += 256) {
        int j = s + t;
        sx[t] = pos[3 * j + 0];
        sy[t] = pos[3 * j + 1];
        sz[t] = pos[3 * j + 2];
        float qv = g_q[j];
        sq[t] = qv;  qacc += qv;
        sc[t] = g_sc6[j];
        sr[t] = g_r3[j];
    }
#pragma unroll
    for (int o = 16; o > 0; o >>= 1) qacc += __shfl_xor_sync(0xFFFFFFFFu, qacc, o);
    if (lane == 0) wred[wrp] = qacc;
    __syncthreads();
    if (tid == 0) {
        float t = 0.f;
        for (int w = 0; w < 8; w++) t += wred[w];
        s_qm = t / fmaxf((float)c, 1.0f);
    }
    __syncthreads();
    const float qm = s_qm;
    for (int t = tid; t < c; t += 256) sq[t] -= qm;
    __syncthreads();

    const float invs = 1.0f / (1.41421356f * sigma[0]);

    float eel = 0.f, evd = 0.f;
    for (int i = wrp; i < c; i += 8) {
        float px = sx[i], py = sy[i], pz = sz[i];
        float qi = sq[i], c6i = sc[i], r3i = sr[i];
        for (int j = i + 1 + lane; j < c; j += 32) {
            float dx = px - sx[j];
            float dy = py - sy[j];
            float dz = pz - sz[j];
            float dsq = dx * dx + dy * dy + dz * dz;
            float dist = sqrtf(dsq + 1e-8f);
            eel += qi * sq[j] * __fdividef(erff(dist * invs), dist + 1e-8f);
            float damp = dsq * dsq * dsq + r3i * sr[j];
            evd -= __fdividef(c6i * sc[j], damp + 1e-8f);
        }
    }

    float tot = KE_CONST * eel + evd;   // unordered pairs: 2 * 0.5 = 1
#pragma unroll
    for (int o = 16; o > 0; o >>= 1) tot += __shfl_down_sync(0xFFFFFFFFu, tot, o);
    if (lane == 0) wred[wrp] = tot;
    __syncthreads();
    if (tid == 0) {
        float bs = 0.f;
        for (int w = 0; w < 8; w++) bs += wred[w];
        atomicAdd(&g_esum, (double)bs);
        __threadfence();
        unsigned t = atomicAdd(&g_done, 1u);
        if (t == gridDim.x - 1) {
            g_done = 0u;
            double total = atomicAdd(&g_esum, 0.0);
            out[0] = (float)total;
        }
    }
}

// ---------------- launch ----------------
extern "C" void kernel_launch(void* const* d_in, const int* in_sizes, int n_in,
                              void* d_out, int out_size) {
    const float* h0    = (const float*)d_in[0];
    const float* pos   = (const float*)d_in[2];
    const float* qW1   = (const float*)d_in[3];
    const float* qb1   = (const float*)d_in[4];
    const float* qW2   = (const float*)d_in[5];
    const float* sigma = (const float*)d_in[6];
    const float* vW1   = (const float*)d_in[7];
    const float* vb1   = (const float*)d_in[8];
    const float* vW2   = (const float*)d_in[9];
    const float* vb2   = (const float*)d_in[10];
    const int*   batch = (const int*)d_in[11];

    mlp_gemm_kernel<<<2 * MTILES + 1, 128>>>(h0, qW1, qb1, qW2,
                                             vW1, vb1, vW2, vb2, batch);
    pair_kernel<<<G, 256>>>(pos, sigma, (float*)d_out);
}

// round 13
// speedup vs baseline: 1.5625x; 1.5625x over previous
#include <cuda_runtime.h>
#include <cuda_bf16.h>
#include <cstdint>

#define NATOMS 6144
#define F 128
#define G 48
#define MTILES 48              // 48 m-tiles of 128 atoms
#define SPLIT 12               // pair blocks per graph
#define MAXC 256
#define KE_CONST 14.3996f

// smem layout (bytes): bf16 tiles with 136-element (272B) row stride
#define RS 136
#define TILE_B (128 * RS * 2)          // 34816
#define SM_AHI  0
#define SM_ALO  (SM_AHI + TILE_B)
#define SM_BHI  (SM_ALO + TILE_B)
#define SM_BLO  (SM_BHI + TILE_B)
#define SM_B1   (SM_BLO + TILE_B)      // 128 floats
#define SM_W2A  (SM_B1  + 512)
#define SM_W2B  (SM_W2A + 512)
#define SM_RED0 (SM_W2B + 512)
#define SM_RED1 (SM_RED0 + 512)
#define SM_TOTAL (SM_RED1 + 512)       // 141824

// ---------------- scratch ----------------
__device__ float    g_q[NATOMS];
__device__ float    g_sc6[NATOMS];
__device__ float    g_r3[NATOMS];
__device__ int      g_start[G];
__device__ int      g_cnt[G];
__device__ double   g_esum;
__device__ unsigned g_done;

__device__ __forceinline__ float softplusf(float x) {
    return fmaxf(x, 0.0f) + log1pf(expf(-fabsf(x)));
}
__device__ __forceinline__ float siluf(float x) {
    return x / (1.0f + expf(-x));
}
__device__ __forceinline__ uint32_t smem_to_u32(const void* p) {
    uint32_t addr;
    asm("{ .reg .u64 tmp; cvta.to.shared.u64 tmp, %1; cvt.u32.u64 %0, tmp; }"
        : "=r"(addr) : "l"(p));
    return addr;
}
__device__ __forceinline__ uint32_t pack_bf16x2(__nv_bfloat16 a, __nv_bfloat16 b) {
    return (uint32_t)__bfloat16_as_ushort(a) | ((uint32_t)__bfloat16_as_ushort(b) << 16);
}
__device__ __forceinline__ void ldm4(uint32_t r[4], uint32_t addr) {
    asm volatile("ldmatrix.sync.aligned.m8n8.x4.shared.b16 {%0,%1,%2,%3}, [%4];"
        : "=r"(r[0]), "=r"(r[1]), "=r"(r[2]), "=r"(r[3]) : "r"(addr));
}
__device__ __forceinline__ void mma16816(float c[4], const uint32_t a[4],
                                         uint32_t b0, uint32_t b1) {
    asm volatile(
        "mma.sync.aligned.m16n8k16.row.col.f32.bf16.bf16.f32 "
        "{%0,%1,%2,%3}, {%4,%5,%6,%7}, {%8,%9}, {%0,%1,%2,%3};"
        : "+f"(c[0]), "+f"(c[1]), "+f"(c[2]), "+f"(c[3])
        : "r"(a[0]), "r"(a[1]), "r"(a[2]), "r"(a[3]), "r"(b0), "r"(b1));
}

// ================= K1: MLP via warp-level bf16 MMA (hi/lo 3-term) =========
// grid = 2*MTILES + 1 = 97 blocks x 256 threads.
// bid < 96: head = bid/48, m-tile = bid%48 (128 atoms). Last block: service.
// 8 warps as 4(m) x 2(n): warp = rows [wm*32,+32), cols [wn*64,+64).
__global__ __launch_bounds__(256) void mlp_mma_kernel(
    const float* __restrict__ h0,
    const float* __restrict__ qW1, const float* __restrict__ qb1,
    const float* __restrict__ qW2,
    const float* __restrict__ vW1, const float* __restrict__ vb1,
    const float* __restrict__ vW2, const float* __restrict__ vb2,
    const int*   __restrict__ batch)
{
    const int bid = blockIdx.x;
    const int tid = threadIdx.x;

    if (bid == 2 * MTILES) {
        if (tid == 0) { g_esum = 0.0; g_done = 0u; }
        __shared__ int ss[G + 1];
        if (tid <= G) {
            int lo = 0, hi = NATOMS;
            while (lo < hi) {
                int m = (lo + hi) >> 1;
                if (batch[m] < tid) lo = m + 1; else hi = m;
            }
            ss[tid] = lo;
        }
        __syncthreads();
        if (tid < G) { g_start[tid] = ss[tid]; g_cnt[tid] = ss[tid + 1] - ss[tid]; }
        return;
    }

    extern __shared__ char smem[];
    const int head  = bid / MTILES;
    const int mbase = (bid % MTILES) * F;

    const float* __restrict__ W1 = head ? vW1 : qW1;
    const float* __restrict__ B1 = head ? vb1 : qb1;

    float* b1s  = (float*)(smem + SM_B1);
    float* w2as = (float*)(smem + SM_W2A);
    float* w2bs = (float*)(smem + SM_W2B);
    float* red0 = (float*)(smem + SM_RED0);
    float* red1 = (float*)(smem + SM_RED1);

    if (tid < F) {
        b1s[tid] = B1[tid];
        if (head) { w2as[tid] = vW2[2 * tid]; w2bs[tid] = vW2[2 * tid + 1]; }
        else      { w2as[tid] = qW2[tid];     w2bs[tid] = 0.0f; }
    }

    // ---- A convert: h0 tile -> Ahi/Alo [m][k] bf16 ----
    {
        const int row = tid >> 1;
        const int seg = (tid & 1) * 64;
        const float4* src = (const float4*)(h0 + (size_t)(mbase + row) * F + seg);
        uint32_t* dhi = (uint32_t*)(smem + SM_AHI) + (row * RS + seg) / 2;
        uint32_t* dlo = (uint32_t*)(smem + SM_ALO) + (row * RS + seg) / 2;
#pragma unroll
        for (int j = 0; j < 16; j++) {
            float4 v = src[j];
            __nv_bfloat16 hx = __float2bfloat16(v.x), hy = __float2bfloat16(v.y);
            __nv_bfloat16 hz = __float2bfloat16(v.z), hw = __float2bfloat16(v.w);
            __nv_bfloat16 lx = __float2bfloat16(v.x - __bfloat162float(hx));
            __nv_bfloat16 ly = __float2bfloat16(v.y - __bfloat162float(hy));
            __nv_bfloat16 lz = __float2bfloat16(v.z - __bfloat162float(hz));
            __nv_bfloat16 lw = __float2bfloat16(v.w - __bfloat162float(hw));
            dhi[2 * j + 0] = pack_bf16x2(hx, hy);
            dhi[2 * j + 1] = pack_bf16x2(hz, hw);
            dlo[2 * j + 0] = pack_bf16x2(lx, ly);
            dlo[2 * j + 1] = pack_bf16x2(lz, lw);
        }
    }

    // ---- B convert + transpose: W1[k][n] -> Bhi/Blo [n][k] bf16 ----
    {
        const int k    = tid >> 1;
        const int nseg = (tid & 1) * 64;
        const float4* src = (const float4*)(W1 + (size_t)k * F + nseg);
        __nv_bfloat16* bhi = (__nv_bfloat16*)(smem + SM_BHI);
        __nv_bfloat16* blo = (__nv_bfloat16*)(smem + SM_BLO);
#pragma unroll
        for (int j = 0; j < 16; j++) {
            float4 v = src[j];
            float vv[4] = {v.x, v.y, v.z, v.w};
#pragma unroll
            for (int e = 0; e < 4; e++) {
                int n = nseg + 4 * j + e;
                __nv_bfloat16 hb = __float2bfloat16(vv[e]);
                __nv_bfloat16 lb = __float2bfloat16(vv[e] - __bfloat162float(hb));
                bhi[n * RS + k] = hb;
                blo[n * RS + k] = lb;
            }
        }
    }
    __syncthreads();

    // ---- MMA mainloop ----
    const int wid = tid >> 5, lane = tid & 31;
    const int wm = wid >> 1, wn = wid & 1;
    const int m0 = wm * 32;

    float acc[2][8][4];
#pragma unroll
    for (int mt = 0; mt < 2; mt++)
#pragma unroll
        for (int nt = 0; nt < 8; nt++)
#pragma unroll
            for (int e = 0; e < 4; e++) acc[mt][nt][e] = 0.0f;

    const uint32_t sb = smem_to_u32(smem);
    uint32_t aHi[2], aLo[2], bHi[4], bLo[4];
#pragma unroll
    for (int mt = 0; mt < 2; mt++) {
        int rowA = m0 + mt * 16 + (lane & 15);
        int colA = (lane >> 4) * 8;
        aHi[mt] = sb + SM_AHI + (rowA * RS + colA) * 2;
        aLo[mt] = sb + SM_ALO + (rowA * RS + colA) * 2;
    }
#pragma unroll
    for (int p = 0; p < 4; p++) {
        int nB = wn * 64 + p * 16 + (lane & 7) + ((lane >> 4) & 1) * 8;
        int kB = ((lane >> 3) & 1) * 8;
        bHi[p] = sb + SM_BHI + (nB * RS + kB) * 2;
        bLo[p] = sb + SM_BLO + (nB * RS + kB) * 2;
    }

#pragma unroll
    for (int s = 0; s < 8; s++) {
        uint32_t ah[2][4], al[2][4], bh[4][4], bl[4][4];
#pragma unroll
        for (int mt = 0; mt < 2; mt++) {
            ldm4(ah[mt], aHi[mt]); aHi[mt] += 32;
            ldm4(al[mt], aLo[mt]); aLo[mt] += 32;
        }
#pragma unroll
        for (int p = 0; p < 4; p++) {
            ldm4(bh[p], bHi[p]); bHi[p] += 32;
            ldm4(bl[p], bLo[p]); bLo[p] += 32;
        }
#pragma unroll
        for (int mt = 0; mt < 2; mt++) {
#pragma unroll
            for (int p = 0; p < 4; p++) {
                mma16816(acc[mt][2 * p],     ah[mt], bh[p][0], bh[p][1]);
                mma16816(acc[mt][2 * p],     al[mt], bh[p][0], bh[p][1]);
                mma16816(acc[mt][2 * p],     ah[mt], bl[p][0], bl[p][1]);
                mma16816(acc[mt][2 * p + 1], ah[mt], bh[p][2], bh[p][3]);
                mma16816(acc[mt][2 * p + 1], al[mt], bh[p][2], bh[p][3]);
                mma16816(acc[mt][2 * p + 1], ah[mt], bl[p][2], bl[p][3]);
            }
        }
    }

    // ---- epilogue: silu + layer-2 dot + reduce ----
    float s0p[2][2], s1p[2][2];
#pragma unroll
    for (int mt = 0; mt < 2; mt++)
#pragma unroll
        for (int rh = 0; rh < 2; rh++) { s0p[mt][rh] = 0.f; s1p[mt][rh] = 0.f; }

#pragma unroll
    for (int mt = 0; mt < 2; mt++)
#pragma unroll
        for (int nt = 0; nt < 8; nt++)
#pragma unroll
            for (int e = 0; e < 4; e++) {
                int n = wn * 64 + nt * 8 + (lane & 3) * 2 + (e & 1);
                float h = siluf(acc[mt][nt][e] + b1s[n]);
                s0p[mt][e >> 1] += h * w2as[n];
                s1p[mt][e >> 1] += h * w2bs[n];
            }

#pragma unroll
    for (int mt = 0; mt < 2; mt++)
#pragma unroll
        for (int rh = 0; rh < 2; rh++) {
            float v0 = s0p[mt][rh], v1 = s1p[mt][rh];
            v0 += __shfl_xor_sync(0xFFFFFFFFu, v0, 1);
            v0 += __shfl_xor_sync(0xFFFFFFFFu, v0, 2);
            v1 += __shfl_xor_sync(0xFFFFFFFFu, v1, 1);
            v1 += __shfl_xor_sync(0xFFFFFFFFu, v1, 2);
            s0p[mt][rh] = v0; s1p[mt][rh] = v1;
        }

    if ((lane & 3) == 0 && wn == 0) {
#pragma unroll
        for (int mt = 0; mt < 2; mt++)
#pragma unroll
            for (int rh = 0; rh < 2; rh++) {
                int r = m0 + mt * 16 + (lane >> 2) + rh * 8;
                red0[r] = s0p[mt][rh];
                red1[r] = s1p[mt][rh];
            }
    }
    __syncthreads();
    if ((lane & 3) == 0 && wn == 1) {
#pragma unroll
        for (int mt = 0; mt < 2; mt++)
#pragma unroll
            for (int rh = 0; rh < 2; rh++) {
                int r = m0 + mt * 16 + (lane >> 2) + rh * 8;
                red0[r] += s0p[mt][rh];
                red1[r] += s1p[mt][rh];
            }
    }
    __syncthreads();

    if (tid < F) {
        int atom = mbase + tid;
        float s0 = red0[tid], s1 = red1[tid];
        if (head == 0) {
            g_q[atom] = s0;
        } else {
            float c6 = softplusf(s0 + vb2[0]);
            float rv = softplusf(s1 + vb2[1]);
            g_sc6[atom] = sqrtf(c6);
            g_r3[atom]  = rv * rv * rv;
        }
    }
}

// ================= K2: pairwise (measured-best: SPLIT 12, 128 thr) =========
__global__ __launch_bounds__(128) void pair_kernel(
    const float* __restrict__ pos,
    const float* __restrict__ sigma,
    float* __restrict__ out)
{
    __shared__ float sx[MAXC], sy[MAXC], sz[MAXC];
    __shared__ float sq[MAXC], sc[MAXC], sr[MAXC];
    __shared__ float wred[4];
    __shared__ float s_qm;

    const int bid = blockIdx.x;
    const int g  = bid / SPLIT;
    const int sp = bid % SPLIT;
    const int tid = threadIdx.x;
    const int lane = tid & 31;
    const int wrp  = tid >> 5;

    const int s = g_start[g];
    const int c = g_cnt[g];

    float qacc = 0.f;
    for (int t = tid; t < c; t += 128) {
        int j = s + t;
        sx[t] = pos[3 * j + 0];
        sy[t] = pos[3 * j + 1];
        sz[t] = pos[3 * j + 2];
        float qv = g_q[j];
        sq[t] = qv;  qacc += qv;
        sc[t] = g_sc6[j];
        sr[t] = g_r3[j];
    }
#pragma unroll
    for (int o = 16; o > 0; o >>= 1) qacc += __shfl_xor_sync(0xFFFFFFFFu, qacc, o);
    if (lane == 0) wred[wrp] = qacc;
    __syncthreads();
    if (tid == 0) s_qm = (wred[0] + wred[1] + wred[2] + wred[3]) / fmaxf((float)c, 1.0f);
    __syncthreads();
    const float qm = s_qm;
    for (int t = tid; t < c; t += 128) sq[t] -= qm;
    __syncthreads();

    const float invs = 1.0f / (1.41421356f * sigma[0]);
    const int wg = wrp + sp * 4;

    float eel = 0.f, evd = 0.f;
    for (int i = wg; i < c; i += SPLIT * 4) {
        float px = sx[i], py = sy[i], pz = sz[i];
        float qi = sq[i], c6i = sc[i], r3i = sr[i];
        for (int j = i + 1 + lane; j < c; j += 32) {
            float dx = px - sx[j];
            float dy = py - sy[j];
            float dz = pz - sz[j];
            float dsq = dx * dx + dy * dy + dz * dz;
            float dist = sqrtf(dsq + 1e-8f);
            eel += qi * sq[j] * __fdividef(erff(dist * invs), dist + 1e-8f);
            float damp = dsq * dsq * dsq + r3i * sr[j];
            evd -= __fdividef(c6i * sc[j], damp + 1e-8f);
        }
    }

    float tot = KE_CONST * eel + evd;   // unordered pairs: 2 * 0.5 = 1
#pragma unroll
    for (int o = 16; o > 0; o >>= 1) tot += __shfl_down_sync(0xFFFFFFFFu, tot, o);
    if (lane == 0) wred[wrp] = tot;
    __syncthreads();
    if (tid == 0) {
        double bsum = (double)(wred[0] + wred[1] + wred[2] + wred[3]);
        atomicAdd(&g_esum, bsum);
        __threadfence();
        unsigned t = atomicAdd(&g_done, 1u);
        if (t == gridDim.x - 1) {
            g_done = 0u;
            double total = atomicAdd(&g_esum, 0.0);
            out[0] = (float)total;
        }
    }
}

// ---------------- launch ----------------
extern "C" void kernel_launch(void* const* d_in, const int* in_sizes, int n_in,
                              void* d_out, int out_size) {
    const float* h0    = (const float*)d_in[0];
    const float* pos   = (const float*)d_in[2];
    const float* qW1   = (const float*)d_in[3];
    const float* qb1   = (const float*)d_in[4];
    const float* qW2   = (const float*)d_in[5];
    const float* sigma = (const float*)d_in[6];
    const float* vW1   = (const float*)d_in[7];
    const float* vb1   = (const float*)d_in[8];
    const float* vW2   = (const float*)d_in[9];
    const float* vb2   = (const float*)d_in[10];
    const int*   batch = (const int*)d_in[11];

    cudaFuncSetAttribute(mlp_mma_kernel,
                         cudaFuncAttributeMaxDynamicSharedMemorySize, SM_TOTAL);

    mlp_mma_kernel<<<2 * MTILES + 1, 256, SM_TOTAL>>>(h0, qW1, qb1, qW2,
                                                      vW1, vb1, vW2, vb2, batch);
    pair_kernel<<<G * SPLIT, 128>>>(pos, sigma, (float*)d_out);
}